// round 8
// baseline (speedup 1.0000x reference)
#include <cuda_runtime.h>
#include <cuda_bf16.h>
#include <cstdint>

#define PW0f 0.08838834764831845f
#define INV_SQRT3f 0.5773502691896258f
#define OUT_STRIDE 896

// ---------------- helpers ----------------
__device__ __forceinline__ uint32_t smem_u32(const void* p) {
    uint32_t a;
    asm("{ .reg .u64 t; cvta.to.shared.u64 t, %1; cvt.u32.u64 %0, t; }" : "=r"(a) : "l"(p));
    return a;
}
__device__ __forceinline__ void ldsm4(uint32_t addr, uint32_t& r0, uint32_t& r1,
                                      uint32_t& r2, uint32_t& r3) {
    asm volatile("ldmatrix.sync.aligned.m8n8.x4.shared.b16 {%0,%1,%2,%3}, [%4];"
                 : "=r"(r0), "=r"(r1), "=r"(r2), "=r"(r3) : "r"(addr));
}
__device__ __forceinline__ void ldsm2(uint32_t addr, uint32_t& r0, uint32_t& r1) {
    asm volatile("ldmatrix.sync.aligned.m8n8.x2.shared.b16 {%0,%1}, [%2];"
                 : "=r"(r0), "=r"(r1) : "r"(addr));
}
__device__ __forceinline__ void mma16816(float* d, const uint32_t* a,
                                         uint32_t b0, uint32_t b1) {
    asm volatile("mma.sync.aligned.m16n8k16.row.col.f32.bf16.bf16.f32 "
                 "{%0,%1,%2,%3}, {%4,%5,%6,%7}, {%8,%9}, {%0,%1,%2,%3};"
                 : "+f"(d[0]), "+f"(d[1]), "+f"(d[2]), "+f"(d[3])
                 : "r"(a[0]), "r"(a[1]), "r"(a[2]), "r"(a[3]), "r"(b0), "r"(b1));
}
__device__ __forceinline__ void bsplit(float f, unsigned short& h, unsigned short& l) {
    __nv_bfloat16 hb = __float2bfloat16(f);
    __nv_bfloat16 lb = __float2bfloat16(f - __bfloat162float(hb));
    h = __bfloat16_as_ushort(hb);
    l = __bfloat16_as_ushort(lb);
}
__device__ __forceinline__ void packsplit2(float f0, float f1, uint32_t& hp, uint32_t& lp) {
    unsigned short h0, l0, h1, l1;
    bsplit(f0, h0, l0); bsplit(f1, h1, l1);
    hp = (uint32_t)h0 | ((uint32_t)h1 << 16);
    lp = (uint32_t)l0 | ((uint32_t)l1 << 16);
}

// ===========================================================================
// Kernel A: o0 (cols 0..319).  Chunk 64 rows.
//   16 warps = 2 m-groups (32 rows, 2 mtiles) x 8 n-groups (40 cols).
//   Register-held raw input, prefetch next chunk during MMA.
// ===========================================================================
#define A_RT 64
#define AO_WH   0
#define AO_WL   87040
#define AO_AH   174080
#define AO_AL   191488
#define AO_BIAS 208896
#define A_SMEM  210176

__global__ __launch_bounds__(512, 1) void k_o0(
    const float* __restrict__ in1, const float* __restrict__ in2,
    const float* __restrict__ Wa0, const float* __restrict__ Wb1,
    const float* __restrict__ bias, float* __restrict__ out,
    int n, int nChunks)
{
    extern __shared__ char sm[];
    const uint32_t sb = smem_u32(sm);
    const int tid = threadIdx.x, lane = tid & 31, wid = tid >> 5;
    const int wm = wid & 1, wn = wid >> 1;

    // stage weights (transposed [n][k], pitch 272B, hi/lo planes, PW0 folded)
    for (int idx = tid; idx < 64 * 320; idx += 512) {
        int u = idx / 320, col = idx - u * 320;
        unsigned short h, l;
        bsplit(PW0f * Wa0[idx], h, l);
        *(unsigned short*)(sm + AO_WH + col * 272 + 2 * u) = h;
        *(unsigned short*)(sm + AO_WL + col * 272 + 2 * u) = l;
        bsplit(PW0f * INV_SQRT3f * Wb1[idx], h, l);
        *(unsigned short*)(sm + AO_WH + col * 272 + 128 + 2 * u) = h;
        *(unsigned short*)(sm + AO_WL + col * 272 + 128 + 2 * u) = l;
    }
    for (int i = tid; i < 320; i += 512) ((float*)(sm + AO_BIAS))[i] = bias[i];

    // ldmatrix addresses
    const int wlr = (lane & 7) + ((lane >> 4) & 1) * 8;
    const int wkh = (lane >> 3) & 1;
    const uint32_t aHb = sb + AO_AH + (uint32_t)(wm * 32 + (lane & 15)) * 272 + (lane >> 4) * 16;
    const uint32_t aLb = aHb + (AO_AL - AO_AH);
    const uint32_t wHb = sb + AO_WH + (uint32_t)(wn * 40 + wlr) * 272 + wkh * 16;
    const uint32_t wLb = wHb + (AO_WL - AO_WH);
    const uint32_t w2H = sb + AO_WH + (uint32_t)(wn * 40 + 32 + (lane & 7)) * 272 + ((lane >> 3) & 1) * 16;
    const uint32_t w2L = w2H + (AO_WL - AO_WH);

    // raw-input mapping: 8 threads per row
    const int r = tid >> 3, p = tid & 7;
    const int q = p - 2;
    const int jcnt = (q < 2) ? 12 : 10;            // vb vectors (p>=2)
    const int j0   = (q < 2) ? 12 * q : 4 + 10 * q;
    const int nf2  = (p < 2) ? 16 : (3 * jcnt) / 2; // #float2 to load

    float2 raw[18];
    float4 iv = make_float4(0.f, 0.f, 0.f, 0.f);

    int chunk = blockIdx.x;
    {   // prologue load
        int nr = chunk * A_RT + r;
        if (nr < n) {
            iv = *(const float4*)(in2 + (size_t)nr * 4);
            const float2* s = (p < 2) ? (const float2*)(in1 + (size_t)nr * 256 + 32 * p)
                                      : (const float2*)(in1 + (size_t)nr * 256 + 64 + 3 * j0);
            #pragma unroll
            for (int i = 0; i < 18; i++) if (i < nf2) raw[i] = s[i];
        }
    }
    __syncthreads();   // weights staged

    for (; chunk < nChunks; chunk += gridDim.x) {
        const int row0 = chunk * A_RT;

        // ---- convert + STS ----
        {
            char* rowH = sm + AO_AH + r * 272;
            char* rowL = sm + AO_AL + r * 272;
            if (p < 2) {
                #pragma unroll
                for (int i = 0; i < 16; i++) {
                    uint32_t hp, lp;
                    packsplit2(raw[i].x * iv.x, raw[i].y * iv.x, hp, lp);
                    *(uint32_t*)(rowH + 64 * p + 4 * i) = hp;
                    *(uint32_t*)(rowL + 64 * p + 4 * i) = lp;
                }
            } else {
                #pragma unroll
                for (int jj = 0; jj < 6; jj++) if (2 * jj < jcnt) {
                    float d0 = raw[3*jj].x * iv.y + raw[3*jj].y * iv.z + raw[3*jj+1].x * iv.w;
                    float d1 = raw[3*jj+1].y * iv.y + raw[3*jj+2].x * iv.z + raw[3*jj+2].y * iv.w;
                    uint32_t hp, lp;
                    packsplit2(d0, d1, hp, lp);
                    int boff = 2 * (64 + j0 + 2 * jj);
                    *(uint32_t*)(rowH + boff) = hp;
                    *(uint32_t*)(rowL + boff) = lp;
                }
            }
        }
        __syncthreads();

        // ---- prefetch next chunk into registers (overlaps MMA) ----
        {
            int nc = chunk + gridDim.x;
            int nr = nc * A_RT + r;
            if (nc < nChunks && nr < n) {
                iv = *(const float4*)(in2 + (size_t)nr * 4);
                const float2* s = (p < 2) ? (const float2*)(in1 + (size_t)nr * 256 + 32 * p)
                                          : (const float2*)(in1 + (size_t)nr * 256 + 64 + 3 * j0);
                #pragma unroll
                for (int i = 0; i < 18; i++) if (i < nf2) raw[i] = s[i];
            }
        }

        // ---- MMA ----
        float d[2][5][4];
        #pragma unroll
        for (int mt = 0; mt < 2; mt++)
            #pragma unroll
            for (int nt = 0; nt < 5; nt++)
                #pragma unroll
                for (int z = 0; z < 4; z++) d[mt][nt][z] = 0.f;

        #pragma unroll
        for (int ks = 0; ks < 8; ks++) {
            uint32_t a0h[4], a1h[4], a0l[4], a1l[4];
            ldsm4(aHb + ks * 32,        a0h[0], a0h[1], a0h[2], a0h[3]);
            ldsm4(aHb + 4352 + ks * 32, a1h[0], a1h[1], a1h[2], a1h[3]);
            ldsm4(aLb + ks * 32,        a0l[0], a0l[1], a0l[2], a0l[3]);
            ldsm4(aLb + 4352 + ks * 32, a1l[0], a1l[1], a1l[2], a1l[3]);
            #pragma unroll
            for (int ntp = 0; ntp < 2; ntp++) {
                uint32_t wh[4], wl[4];
                ldsm4(wHb + ntp * 4352 + ks * 32, wh[0], wh[1], wh[2], wh[3]);
                ldsm4(wLb + ntp * 4352 + ks * 32, wl[0], wl[1], wl[2], wl[3]);
                mma16816(d[0][2*ntp],   a0h, wh[0], wh[1]);
                mma16816(d[0][2*ntp],   a0h, wl[0], wl[1]);
                mma16816(d[0][2*ntp],   a0l, wh[0], wh[1]);
                mma16816(d[0][2*ntp+1], a0h, wh[2], wh[3]);
                mma16816(d[0][2*ntp+1], a0h, wl[2], wl[3]);
                mma16816(d[0][2*ntp+1], a0l, wh[2], wh[3]);
                mma16816(d[1][2*ntp],   a1h, wh[0], wh[1]);
                mma16816(d[1][2*ntp],   a1h, wl[0], wl[1]);
                mma16816(d[1][2*ntp],   a1l, wh[0], wh[1]);
                mma16816(d[1][2*ntp+1], a1h, wh[2], wh[3]);
                mma16816(d[1][2*ntp+1], a1h, wl[2], wl[3]);
                mma16816(d[1][2*ntp+1], a1l, wh[2], wh[3]);
            }
            uint32_t t2h[2], t2l[2];
            ldsm2(w2H + ks * 32, t2h[0], t2h[1]);
            ldsm2(w2L + ks * 32, t2l[0], t2l[1]);
            mma16816(d[0][4], a0h, t2h[0], t2h[1]);
            mma16816(d[0][4], a0h, t2l[0], t2l[1]);
            mma16816(d[0][4], a0l, t2h[0], t2h[1]);
            mma16816(d[1][4], a1h, t2h[0], t2h[1]);
            mma16816(d[1][4], a1h, t2l[0], t2l[1]);
            mma16816(d[1][4], a1l, t2h[0], t2h[1]);
        }

        // ---- epilogue ----
        {
            const float* sBias = (const float*)(sm + AO_BIAS);
            #pragma unroll
            for (int mt = 0; mt < 2; mt++) {
                int rr0 = row0 + wm * 32 + mt * 16 + (lane >> 2);
                int rr1 = rr0 + 8;
                #pragma unroll
                for (int nt = 0; nt < 5; nt++) {
                    int col = wn * 40 + nt * 8 + (lane & 3) * 2;
                    float b0 = sBias[col], b1 = sBias[col + 1];
                    if (rr0 < n) {
                        float2 v = { d[mt][nt][0] + b0, d[mt][nt][1] + b1 };
                        *(float2*)(out + (size_t)rr0 * OUT_STRIDE + col) = v;
                    }
                    if (rr1 < n) {
                        float2 v = { d[mt][nt][2] + b0, d[mt][nt][3] + b1 };
                        *(float2*)(out + (size_t)rr1 * OUT_STRIDE + col) = v;
                    }
                }
            }
        }
        __syncthreads();
    }
}

// ===========================================================================
// Kernel B: o1 (320..703), o2 (704..895).  Chunk 32 rows.
//   A rows 0..31 = sa; 32..127 = vb flat (3r+k).  K=64, pitch 144B.
//   G1 (warps 0-3):  1 m-group (32r, 2mt) x 4 n-groups (32 cols)
//   G2 (warps 4-15): 3 m-groups (32r, 2mt) x 4 n-groups (48 cols)
//   Register raw prefetch; epilogue via smem staging (round-5-proven).
// ===========================================================================
#define B_RT 32
#define BO_WA1H 0
#define BO_WA1L 18432
#define BO_WBCH 36864
#define BO_WBCL 64512
#define BO_AH   92160
#define BO_AL   110592
#define BO_A1   129024
#define BO_G2   145920
#define BO_I2   221184
#define B_SMEM  221696

__global__ __launch_bounds__(512, 1) void k_o12(
    const float* __restrict__ in1, const float* __restrict__ in2,
    const float* __restrict__ Wa1, const float* __restrict__ Wb0,
    const float* __restrict__ Wo2, float* __restrict__ out,
    int n, int nChunks)
{
    extern __shared__ char sm[];
    const uint32_t sb = smem_u32(sm);
    const int tid = threadIdx.x, lane = tid & 31, wid = tid >> 5;

    // stage weights [n][u], pitch 144B, PW0 folded
    for (int idx = tid; idx < 64 * 128; idx += 512) {
        int u = idx >> 7, w = idx & 127;
        unsigned short h, l;
        bsplit(PW0f * Wa1[idx], h, l);
        *(unsigned short*)(sm + BO_WA1H + w * 144 + 2 * u) = h;
        *(unsigned short*)(sm + BO_WA1L + w * 144 + 2 * u) = l;
    }
    for (int idx = tid; idx < 64 * 192; idx += 512) {
        int u = idx / 192, nn = idx - u * 192;
        float v = (nn < 128) ? Wb0[u * 128 + nn] : Wo2[u * 64 + (nn - 128)];
        unsigned short h, l;
        bsplit(PW0f * v, h, l);
        *(unsigned short*)(sm + BO_WBCH + nn * 144 + 2 * u) = h;
        *(unsigned short*)(sm + BO_WBCL + nn * 144 + 2 * u) = l;
    }

    // warp config
    const bool isG1 = (wid < 4);
    int rowbase, colbase;
    uint32_t wBase, wLd;
    if (isG1) { rowbase = 0; colbase = wid * 32; wBase = BO_WA1H; wLd = BO_WA1L - BO_WA1H; }
    else {
        int ix = wid - 4;
        int mg = ix % 3, ng = ix / 3;
        rowbase = 32 + mg * 32; colbase = ng * 48;
        wBase = BO_WBCH; wLd = BO_WBCL - BO_WBCH;
    }
    const int wlr = (lane & 7) + ((lane >> 4) & 1) * 8;
    const int wkh = (lane >> 3) & 1;
    const uint32_t aHb = sb + BO_AH + (uint32_t)(rowbase + (lane & 15)) * 144 + (lane >> 4) * 16;
    const uint32_t aLb = aHb + (BO_AL - BO_AH);
    const uint32_t wHb = sb + wBase + (uint32_t)(colbase + wlr) * 144 + wkh * 16;
    const uint32_t wLb = wHb + wLd;

    float* sA1f = (float*)(sm + BO_A1);
    float* sG2f = (float*)(sm + BO_G2);
    float* sI2  = (float*)(sm + BO_I2);

    // raw mapping: 16 threads per row
    const int r = tid >> 4, p = tid & 15;
    const int q = p - 4;
    const int jcnt = (q < 8) ? 6 : 4;
    const int j0   = (q < 8) ? 6 * q : 16 + 4 * q;
    const int nf2  = (p < 4) ? 8 : (3 * jcnt) / 2;

    float2 raw[9];
    float i2v = 0.f;

    int chunk = blockIdx.x;
    {   // prologue load
        int nr = chunk * B_RT + r;
        if (nr < n) {
            const float2* s = (p < 4) ? (const float2*)(in1 + (size_t)nr * 256 + 16 * p)
                                      : (const float2*)(in1 + (size_t)nr * 256 + 64 + 3 * j0);
            #pragma unroll
            for (int i = 0; i < 9; i++) if (i < nf2) raw[i] = s[i];
        }
        if (tid < 128) {
            int rr = tid >> 2, cc = tid & 3;
            int nr2 = chunk * B_RT + rr;
            if (nr2 < n) i2v = in2[(size_t)nr2 * 4 + cc];
        }
    }
    __syncthreads();   // weights staged

    const int k1a[3] = {1, 2, 0}, k2a[3] = {2, 0, 1};

    for (; chunk < nChunks; chunk += gridDim.x) {
        const int row0 = chunk * B_RT;

        // ---- convert + STS ----
        if (tid < 128) sI2[tid] = i2v;
        {
            if (p < 4) {
                char* rowH = sm + BO_AH + r * 144;
                char* rowL = sm + BO_AL + r * 144;
                #pragma unroll
                for (int i = 0; i < 8; i++) {
                    uint32_t hp, lp;
                    packsplit2(raw[i].x, raw[i].y, hp, lp);
                    *(uint32_t*)(rowH + 32 * p + 4 * i) = hp;
                    *(uint32_t*)(rowL + 32 * p + 4 * i) = lp;
                }
            } else {
                #pragma unroll
                for (int jj = 0; jj < 3; jj++) if (2 * jj < jcnt) {
                    int j = j0 + 2 * jj;
                    float v0[3], v1[3];
                    v0[0] = raw[3*jj].x;   v1[0] = raw[3*jj+1].y;
                    v0[1] = raw[3*jj].y;   v1[1] = raw[3*jj+2].x;
                    v0[2] = raw[3*jj+1].x; v1[2] = raw[3*jj+2].y;
                    #pragma unroll
                    for (int kk = 0; kk < 3; kk++) {
                        uint32_t hp, lp;
                        packsplit2(v0[kk], v1[kk], hp, lp);
                        int rw = 32 + 3 * r + kk;
                        *(uint32_t*)(sm + BO_AH + rw * 144 + 2 * j) = hp;
                        *(uint32_t*)(sm + BO_AL + rw * 144 + 2 * j) = lp;
                    }
                }
            }
        }
        __syncthreads();

        // ---- prefetch next chunk (overlaps MMA) ----
        {
            int nc = chunk + gridDim.x;
            if (nc < nChunks) {
                int nr = nc * B_RT + r;
                if (nr < n) {
                    const float2* s = (p < 4) ? (const float2*)(in1 + (size_t)nr * 256 + 16 * p)
                                              : (const float2*)(in1 + (size_t)nr * 256 + 64 + 3 * j0);
                    #pragma unroll
                    for (int i = 0; i < 9; i++) if (i < nf2) raw[i] = s[i];
                }
                if (tid < 128) {
                    int rr = tid >> 2, cc = tid & 3;
                    int nr2 = nc * B_RT + rr;
                    if (nr2 < n) i2v = in2[(size_t)nr2 * 4 + cc];
                }
            }
        }

        // ---- MMA + stage results ----
        if (isG1) {
            float d[2][4][4];
            #pragma unroll
            for (int mt = 0; mt < 2; mt++)
                #pragma unroll
                for (int nt = 0; nt < 4; nt++)
                    #pragma unroll
                    for (int z = 0; z < 4; z++) d[mt][nt][z] = 0.f;
            #pragma unroll
            for (int ks = 0; ks < 4; ks++) {
                uint32_t a0h[4], a1h[4], a0l[4], a1l[4];
                ldsm4(aHb + ks * 32,        a0h[0], a0h[1], a0h[2], a0h[3]);
                ldsm4(aHb + 2304 + ks * 32, a1h[0], a1h[1], a1h[2], a1h[3]);
                ldsm4(aLb + ks * 32,        a0l[0], a0l[1], a0l[2], a0l[3]);
                ldsm4(aLb + 2304 + ks * 32, a1l[0], a1l[1], a1l[2], a1l[3]);
                #pragma unroll
                for (int ntp = 0; ntp < 2; ntp++) {
                    uint32_t wh[4], wl[4];
                    ldsm4(wHb + ntp * 2304 + ks * 32, wh[0], wh[1], wh[2], wh[3]);
                    ldsm4(wLb + ntp * 2304 + ks * 32, wl[0], wl[1], wl[2], wl[3]);
                    mma16816(d[0][2*ntp],   a0h, wh[0], wh[1]);
                    mma16816(d[0][2*ntp],   a0h, wl[0], wl[1]);
                    mma16816(d[0][2*ntp],   a0l, wh[0], wh[1]);
                    mma16816(d[0][2*ntp+1], a0h, wh[2], wh[3]);
                    mma16816(d[0][2*ntp+1], a0h, wl[2], wl[3]);
                    mma16816(d[0][2*ntp+1], a0l, wh[2], wh[3]);
                    mma16816(d[1][2*ntp],   a1h, wh[0], wh[1]);
                    mma16816(d[1][2*ntp],   a1h, wl[0], wl[1]);
                    mma16816(d[1][2*ntp],   a1l, wh[0], wh[1]);
                    mma16816(d[1][2*ntp+1], a1h, wh[2], wh[3]);
                    mma16816(d[1][2*ntp+1], a1h, wl[2], wl[3]);
                    mma16816(d[1][2*ntp+1], a1l, wh[2], wh[3]);
                }
            }
            #pragma unroll
            for (int mt = 0; mt < 2; mt++) {
                int m0 = mt * 16 + (lane >> 2);
                #pragma unroll
                for (int nt = 0; nt < 4; nt++) {
                    int c = wid * 32 + nt * 8 + (lane & 3) * 2;
                    sA1f[m0 * 132 + c]           = d[mt][nt][0];
                    sA1f[m0 * 132 + c + 1]       = d[mt][nt][1];
                    sA1f[(m0 + 8) * 132 + c]     = d[mt][nt][2];
                    sA1f[(m0 + 8) * 132 + c + 1] = d[mt][nt][3];
                }
            }
        } else {
            float d[2][6][4];
            #pragma unroll
            for (int mt = 0; mt < 2; mt++)
                #pragma unroll
                for (int nt = 0; nt < 6; nt++)
                    #pragma unroll
                    for (int z = 0; z < 4; z++) d[mt][nt][z] = 0.f;
            #pragma unroll
            for (int ks = 0; ks < 4; ks++) {
                uint32_t a0h[4], a1h[4], a0l[4], a1l[4];
                ldsm4(aHb + ks * 32,        a0h[0], a0h[1], a0h[2], a0h[3]);
                ldsm4(aHb + 2304 + ks * 32, a1h[0], a1h[1], a1h[2], a1h[3]);
                ldsm4(aLb + ks * 32,        a0l[0], a0l[1], a0l[2], a0l[3]);
                ldsm4(aLb + 2304 + ks * 32, a1l[0], a1l[1], a1l[2], a1l[3]);
                #pragma unroll
                for (int ntp = 0; ntp < 3; ntp++) {
                    uint32_t wh[4], wl[4];
                    ldsm4(wHb + ntp * 2304 + ks * 32, wh[0], wh[1], wh[2], wh[3]);
                    ldsm4(wLb + ntp * 2304 + ks * 32, wl[0], wl[1], wl[2], wl[3]);
                    mma16816(d[0][2*ntp],   a0h, wh[0], wh[1]);
                    mma16816(d[0][2*ntp],   a0h, wl[0], wl[1]);
                    mma16816(d[0][2*ntp],   a0l, wh[0], wh[1]);
                    mma16816(d[0][2*ntp+1], a0h, wh[2], wh[3]);
                    mma16816(d[0][2*ntp+1], a0h, wl[2], wl[3]);
                    mma16816(d[0][2*ntp+1], a0l, wh[2], wh[3]);
                    mma16816(d[1][2*ntp],   a1h, wh[0], wh[1]);
                    mma16816(d[1][2*ntp],   a1h, wl[0], wl[1]);
                    mma16816(d[1][2*ntp],   a1l, wh[0], wh[1]);
                    mma16816(d[1][2*ntp+1], a1h, wh[2], wh[3]);
                    mma16816(d[1][2*ntp+1], a1h, wl[2], wl[3]);
                    mma16816(d[1][2*ntp+1], a1l, wh[2], wh[3]);
                }
            }
            int mgrow = rowbase - 32;
            #pragma unroll
            for (int mt = 0; mt < 2; mt++) {
                int m0 = mgrow + mt * 16 + (lane >> 2);
                #pragma unroll
                for (int nt = 0; nt < 6; nt++) {
                    int c = colbase + nt * 8 + (lane & 3) * 2;
                    sG2f[m0 * 196 + c]           = d[mt][nt][0];
                    sG2f[m0 * 196 + c + 1]       = d[mt][nt][1];
                    sG2f[(m0 + 8) * 196 + c]     = d[mt][nt][2];
                    sG2f[(m0 + 8) * 196 + c + 1] = d[mt][nt][3];
                }
            }
        }
        __syncthreads();

        // ---- o1: 32 rows x 384 cols (coalesced) ----
        #pragma unroll
        for (int i = 0; i < 24; i++) {
            int g = tid + i * 512;
            int row = g / 384, c = g - row * 384;
            int w = c / 3, kk = c - 3 * w;
            int nr = row0 + row;
            if (nr < n) {
                float val = sA1f[row * 132 + w] * sI2[row * 4 + 1 + kk]
                          + sG2f[(3 * row + kk) * 196 + w] * sI2[row * 4];
                out[(size_t)nr * OUT_STRIDE + 320 + c] = val;
            }
        }
        // ---- o2: 32 rows x 192 cols (coalesced) ----
        #pragma unroll
        for (int i = 0; i < 12; i++) {
            int g = tid + i * 512;
            int row = g / 192, c = g - row * 192;
            int w = c / 3, kk = c - 3 * w;
            int nr = row0 + row;
            if (nr < n) {
                int k1 = k1a[kk], k2 = k2a[kk];
                float val = sG2f[(3 * row + k1) * 196 + 128 + w] * sI2[row * 4 + 1 + k2]
                          - sG2f[(3 * row + k2) * 196 + 128 + w] * sI2[row * 4 + 1 + k1];
                out[(size_t)nr * OUT_STRIDE + 704 + c] = val;
            }
        }
        __syncthreads();
    }
}

extern "C" void kernel_launch(void* const* d_in, const int* in_sizes, int n_in,
                              void* d_out, int out_size)
{
    const float* in1   = (const float*)d_in[0];
    const float* in2   = (const float*)d_in[1];
    const float* Wa0   = (const float*)d_in[2];
    const float* Wb1o0 = (const float*)d_in[3];
    const float* Wa1   = (const float*)d_in[4];
    const float* Wb0   = (const float*)d_in[5];
    const float* Wo2   = (const float*)d_in[6];
    const float* bias  = (const float*)d_in[7];
    float* out = (float*)d_out;

    const int n = in_sizes[0] / 256;

    cudaFuncSetAttribute(k_o0,  cudaFuncAttributeMaxDynamicSharedMemorySize, A_SMEM);
    cudaFuncSetAttribute(k_o12, cudaFuncAttributeMaxDynamicSharedMemorySize, B_SMEM);

    int sms = 148;
    cudaDeviceGetAttribute(&sms, cudaDevAttrMultiProcessorCount, 0);

    const int chA = (n + A_RT - 1) / A_RT;
    const int chB = (n + B_RT - 1) / B_RT;
    const int gA = sms < chA ? sms : chA;
    const int gB = sms < chB ? sms : chB;

    k_o12<<<gB, 512, B_SMEM>>>(in1, in2, Wa1, Wb0, Wo2, out, n, chB);
    k_o0 <<<gA, 512, A_SMEM>>>(in1, in2, Wa0, Wb1o0, bias, out, n, chA);
}

// round 9
// speedup vs baseline: 1.4859x; 1.4859x over previous
#include <cuda_runtime.h>
#include <cuda_fp16.h>
#include <cstdint>

#define PW0f 0.08838834764831845f
#define INV_SQRT3f 0.5773502691896258f
#define OUT_STRIDE 896

// ---------------- helpers ----------------
__device__ __forceinline__ uint32_t smem_u32(const void* p) {
    uint32_t a;
    asm("{ .reg .u64 t; cvta.to.shared.u64 t, %1; cvt.u32.u64 %0, t; }" : "=r"(a) : "l"(p));
    return a;
}
__device__ __forceinline__ void ldsm4(uint32_t addr, uint32_t& r0, uint32_t& r1,
                                      uint32_t& r2, uint32_t& r3) {
    asm volatile("ldmatrix.sync.aligned.m8n8.x4.shared.b16 {%0,%1,%2,%3}, [%4];"
                 : "=r"(r0), "=r"(r1), "=r"(r2), "=r"(r3) : "r"(addr));
}
__device__ __forceinline__ void mma16816(float* d, const uint32_t* a,
                                         uint32_t b0, uint32_t b1) {
    asm volatile("mma.sync.aligned.m16n8k16.row.col.f32.f16.f16.f32 "
                 "{%0,%1,%2,%3}, {%4,%5,%6,%7}, {%8,%9}, {%0,%1,%2,%3};"
                 : "+f"(d[0]), "+f"(d[1]), "+f"(d[2]), "+f"(d[3])
                 : "r"(a[0]), "r"(a[1]), "r"(a[2]), "r"(a[3]), "r"(b0), "r"(b1));
}
__device__ __forceinline__ unsigned short h16(float f) {
    return __half_as_ushort(__float2half(f));
}
__device__ __forceinline__ uint32_t pack2h(float f0, float f1) {
    return (uint32_t)h16(f0) | ((uint32_t)h16(f1) << 16);
}

// ===========================================================================
// Kernel A: o0 (cols 0..319).  Chunk 64 rows, 256 threads, 2 blocks/SM.
//   A[64][128]fp16 = [sa*s0 | dot(vb,v1)/sqrt3*...]; W[320][128]fp16 (PW0 folded)
//   8 warps = 2 m-groups (32 rows) x 4 n-groups (80 cols).
// ===========================================================================
#define A_RT 64
#define AO_W    0          /* 320 x 272B = 87040 */
#define AO_A    87040      /* 64 x 272B  = 17408 */
#define AO_BIAS 104448     /* 320 x 4    = 1280  */
#define A_SMEM  105728

__global__ __launch_bounds__(256, 2) void k_o0(
    const float* __restrict__ in1, const float* __restrict__ in2,
    const float* __restrict__ Wa0, const float* __restrict__ Wb1,
    const float* __restrict__ bias, float* __restrict__ out,
    int n, int nChunks)
{
    extern __shared__ char sm[];
    const uint32_t sb = smem_u32(sm);
    const int tid = threadIdx.x, lane = tid & 31, wid = tid >> 5;
    const int wm = wid & 1, wn = wid >> 1;

    // stage weights (transposed [n][k], pitch 272B, PW0 folded)
    for (int idx = tid; idx < 64 * 320; idx += 256) {
        int u = idx / 320, col = idx - u * 320;
        *(unsigned short*)(sm + AO_W + col * 272 + 2 * u)       = h16(PW0f * Wa0[idx]);
        *(unsigned short*)(sm + AO_W + col * 272 + 128 + 2 * u) = h16(PW0f * INV_SQRT3f * Wb1[idx]);
    }
    for (int i = tid; i < 320; i += 256) ((float*)(sm + AO_BIAS))[i] = bias[i];

    // ldmatrix addresses
    const int wlr = (lane & 7) + ((lane >> 4) & 1) * 8;
    const int wkh = (lane >> 3) & 1;
    const uint32_t aB = sb + AO_A + (uint32_t)(wm * 32 + (lane & 15)) * 272 + (lane >> 4) * 16;
    const uint32_t wB = sb + AO_W + (uint32_t)(wn * 80 + wlr) * 272 + wkh * 16;

    const int r = tid >> 2, p = tid & 3;   // 4 threads per row

    __syncthreads();

    for (int chunk = blockIdx.x; chunk < nChunks; chunk += gridDim.x) {
        const int row0 = chunk * A_RT;

        // ---- load + convert + STS ----
        {
            int nr = row0 + r;
            char* rowA = sm + AO_A + r * 272;
            if (nr < n) {
                const float* ip = in1 + (size_t)nr * 256;
                float4 iv = *(const float4*)(in2 + (size_t)nr * 4);
                if (p < 2) {
                    const float2* s = (const float2*)(ip + 32 * p);
                    #pragma unroll
                    for (int i = 0; i < 8; i++) {
                        float2 x0 = s[2*i], x1 = s[2*i+1];
                        uint2 v = { pack2h(x0.x * iv.x, x0.y * iv.x),
                                    pack2h(x1.x * iv.x, x1.y * iv.x) };
                        *(uint2*)(rowA + 64 * p + 8 * i) = v;
                    }
                } else {
                    int j0 = 32 * (p - 2);
                    #pragma unroll
                    for (int b = 0; b < 4; b++) {
                        const float* vp = ip + 64 + 3 * j0 + 24 * b;
                        float4 f0 = *(const float4*)(vp);
                        float4 f1 = *(const float4*)(vp + 4);
                        float4 f2 = *(const float4*)(vp + 8);
                        float4 f3 = *(const float4*)(vp + 12);
                        float4 f4 = *(const float4*)(vp + 16);
                        float4 f5 = *(const float4*)(vp + 20);
                        float d0 = f0.x*iv.y + f0.y*iv.z + f0.z*iv.w;
                        float d1 = f0.w*iv.y + f1.x*iv.z + f1.y*iv.w;
                        float d2 = f1.z*iv.y + f1.w*iv.z + f2.x*iv.w;
                        float d3 = f2.y*iv.y + f2.z*iv.z + f2.w*iv.w;
                        float d4 = f3.x*iv.y + f3.y*iv.z + f3.z*iv.w;
                        float d5 = f3.w*iv.y + f4.x*iv.z + f4.y*iv.w;
                        float d6 = f4.z*iv.y + f4.w*iv.z + f5.x*iv.w;
                        float d7 = f5.y*iv.y + f5.z*iv.z + f5.w*iv.w;
                        uint4 v = { pack2h(d0, d1), pack2h(d2, d3),
                                    pack2h(d4, d5), pack2h(d6, d7) };
                        *(uint4*)(rowA + 128 + 2 * j0 + 16 * b) = v;
                    }
                }
            } else {
                if (p < 2) {
                    #pragma unroll
                    for (int i = 0; i < 8; i++) *(uint2*)(rowA + 64 * p + 8 * i) = make_uint2(0, 0);
                } else {
                    int j0 = 32 * (p - 2);
                    #pragma unroll
                    for (int b = 0; b < 4; b++)
                        *(uint4*)(rowA + 128 + 2 * j0 + 16 * b) = make_uint4(0, 0, 0, 0);
                }
            }
        }
        __syncthreads();

        // ---- MMA: single-pass fp16 ----
        float d[2][10][4];
        #pragma unroll
        for (int mt = 0; mt < 2; mt++)
            #pragma unroll
            for (int nt = 0; nt < 10; nt++)
                #pragma unroll
                for (int z = 0; z < 4; z++) d[mt][nt][z] = 0.f;

        #pragma unroll
        for (int ks = 0; ks < 8; ks++) {
            uint32_t a0[4], a1[4];
            ldsm4(aB + ks * 32,        a0[0], a0[1], a0[2], a0[3]);
            ldsm4(aB + 4352 + ks * 32, a1[0], a1[1], a1[2], a1[3]);
            #pragma unroll
            for (int nt2 = 0; nt2 < 5; nt2++) {
                uint32_t w[4];
                ldsm4(wB + nt2 * 4352 + ks * 32, w[0], w[1], w[2], w[3]);
                mma16816(d[0][2*nt2],   a0, w[0], w[1]);
                mma16816(d[0][2*nt2+1], a0, w[2], w[3]);
                mma16816(d[1][2*nt2],   a1, w[0], w[1]);
                mma16816(d[1][2*nt2+1], a1, w[2], w[3]);
            }
        }

        // ---- epilogue: registers -> gmem ----
        {
            const float* sBias = (const float*)(sm + AO_BIAS);
            #pragma unroll
            for (int mt = 0; mt < 2; mt++) {
                int rr0 = row0 + wm * 32 + mt * 16 + (lane >> 2);
                int rr1 = rr0 + 8;
                #pragma unroll
                for (int nt = 0; nt < 10; nt++) {
                    int col = wn * 80 + nt * 8 + (lane & 3) * 2;
                    float b0 = sBias[col], b1 = sBias[col + 1];
                    if (rr0 < n) {
                        float2 v = { d[mt][nt][0] + b0, d[mt][nt][1] + b1 };
                        *(float2*)(out + (size_t)rr0 * OUT_STRIDE + col) = v;
                    }
                    if (rr1 < n) {
                        float2 v = { d[mt][nt][2] + b0, d[mt][nt][3] + b1 };
                        *(float2*)(out + (size_t)rr1 * OUT_STRIDE + col) = v;
                    }
                }
            }
        }
        __syncthreads();
    }
}

// ===========================================================================
// Kernel B: o1 (320..703), o2 (704..895).  Chunk 32 rows, 512 threads.
//   A rows 0..31 = sa; 32..127 = vb flat (3r+k).  K=64 fp16, pitch 144B.
//   G1 (warps 0-3):  32 rows x 32 cols each  -> sA1[32][132]
//   G2 (warps 4-15): 3 m-groups x 4 n-groups (48 cols) -> sG2[96][196]
// ===========================================================================
#define B_RT 32
#define BO_WA1 0           /* 128 x 144 = 18432 */
#define BO_WBC 18432       /* 192 x 144 = 27648 */
#define BO_A   46080       /* 128 x 144 = 18432 */
#define BO_A1  64512       /* 32 x 132 x 4 = 16896 */
#define BO_G2  81408       /* 96 x 196 x 4 = 75264 */
#define BO_I2  156672      /* 128 x 4 = 512 */
#define B_SMEM 157184

__global__ __launch_bounds__(512, 1) void k_o12(
    const float* __restrict__ in1, const float* __restrict__ in2,
    const float* __restrict__ Wa1, const float* __restrict__ Wb0,
    const float* __restrict__ Wo2, float* __restrict__ out,
    int n, int nChunks)
{
    extern __shared__ char sm[];
    const uint32_t sb = smem_u32(sm);
    const int tid = threadIdx.x, lane = tid & 31, wid = tid >> 5;

    // stage weights [n][u] fp16, pitch 144B, PW0 folded
    for (int idx = tid; idx < 64 * 128; idx += 512) {
        int u = idx >> 7, w = idx & 127;
        *(unsigned short*)(sm + BO_WA1 + w * 144 + 2 * u) = h16(PW0f * Wa1[idx]);
    }
    for (int idx = tid; idx < 64 * 192; idx += 512) {
        int u = idx / 192, nn = idx - u * 192;
        float v = (nn < 128) ? Wb0[u * 128 + nn] : Wo2[u * 64 + (nn - 128)];
        *(unsigned short*)(sm + BO_WBC + nn * 144 + 2 * u) = h16(PW0f * v);
    }

    // warp config
    const bool isG1 = (wid < 4);
    int rowbase, colbase;
    uint32_t wBase;
    if (isG1) { rowbase = 0; colbase = wid * 32; wBase = BO_WA1; }
    else {
        int ix = wid - 4;
        int mg = ix % 3, ng = ix / 3;
        rowbase = 32 + mg * 32; colbase = ng * 48;
        wBase = BO_WBC;
    }
    const int wlr = (lane & 7) + ((lane >> 4) & 1) * 8;
    const int wkh = (lane >> 3) & 1;
    const uint32_t aB = sb + BO_A + (uint32_t)(rowbase + (lane & 15)) * 144 + (lane >> 4) * 16;
    const uint32_t wB = sb + wBase + (uint32_t)(colbase + wlr) * 144 + wkh * 16;

    float* sA1f = (float*)(sm + BO_A1);
    float* sG2f = (float*)(sm + BO_G2);
    float* sI2  = (float*)(sm + BO_I2);

    const int r = tid >> 4, p = tid & 15;   // 16 threads per row
    const int q = p - 4;
    const int jcnt = (q < 8) ? 6 : 4;
    const int j0   = (q < 8) ? 6 * q : 16 + 4 * q;  // q>=8: 48 + 4*(q-8)

    const int k1a[3] = {1, 2, 0}, k2a[3] = {2, 0, 1};

    __syncthreads();

    for (int chunk = blockIdx.x; chunk < nChunks; chunk += gridDim.x) {
        const int row0 = chunk * B_RT;

        if (tid < 128) {
            int rr = tid >> 2, cc = tid & 3;
            int nr2 = row0 + rr;
            sI2[tid] = (nr2 < n) ? in2[(size_t)nr2 * 4 + cc] : 0.f;
        }

        // ---- load + convert + STS ----
        {
            int nr = row0 + r;
            if (p < 4) {
                char* rowA = sm + BO_A + r * 144;
                if (nr < n) {
                    const float2* s = (const float2*)(in1 + (size_t)nr * 256 + 16 * p);
                    #pragma unroll
                    for (int i = 0; i < 4; i++) {
                        float2 x0 = s[2*i], x1 = s[2*i+1];
                        uint2 v = { pack2h(x0.x, x0.y), pack2h(x1.x, x1.y) };
                        *(uint2*)(rowA + 32 * p + 8 * i) = v;
                    }
                } else {
                    #pragma unroll
                    for (int i = 0; i < 4; i++) *(uint2*)(rowA + 32 * p + 8 * i) = make_uint2(0, 0);
                }
            } else {
                if (nr < n) {
                    const float2* s = (const float2*)(in1 + (size_t)nr * 256 + 64 + 3 * j0);
                    float2 raw[9];
                    #pragma unroll
                    for (int i = 0; i < 9; i++) if (i < (3 * jcnt) / 2) raw[i] = s[i];
                    #pragma unroll
                    for (int jj = 0; jj < 3; jj++) if (2 * jj < jcnt) {
                        int j = j0 + 2 * jj;
                        float v0[3], v1[3];
                        v0[0] = raw[3*jj].x;   v1[0] = raw[3*jj+1].y;
                        v0[1] = raw[3*jj].y;   v1[1] = raw[3*jj+2].x;
                        v0[2] = raw[3*jj+1].x; v1[2] = raw[3*jj+2].y;
                        #pragma unroll
                        for (int kk = 0; kk < 3; kk++) {
                            int rw = 32 + 3 * r + kk;
                            *(uint32_t*)(sm + BO_A + rw * 144 + 2 * j) = pack2h(v0[kk], v1[kk]);
                        }
                    }
                } else {
                    #pragma unroll
                    for (int jj = 0; jj < 3; jj++) if (2 * jj < jcnt) {
                        int j = j0 + 2 * jj;
                        #pragma unroll
                        for (int kk = 0; kk < 3; kk++) {
                            int rw = 32 + 3 * r + kk;
                            *(uint32_t*)(sm + BO_A + rw * 144 + 2 * j) = 0u;
                        }
                    }
                }
            }
        }
        __syncthreads();

        // ---- MMA (single-pass fp16) + stage results ----
        if (isG1) {
            float d[2][4][4];
            #pragma unroll
            for (int mt = 0; mt < 2; mt++)
                #pragma unroll
                for (int nt = 0; nt < 4; nt++)
                    #pragma unroll
                    for (int z = 0; z < 4; z++) d[mt][nt][z] = 0.f;
            #pragma unroll
            for (int ks = 0; ks < 4; ks++) {
                uint32_t a0[4], a1[4];
                ldsm4(aB + ks * 32,        a0[0], a0[1], a0[2], a0[3]);
                ldsm4(aB + 2304 + ks * 32, a1[0], a1[1], a1[2], a1[3]);
                #pragma unroll
                for (int ntp = 0; ntp < 2; ntp++) {
                    uint32_t w[4];
                    ldsm4(wB + ntp * 2304 + ks * 32, w[0], w[1], w[2], w[3]);
                    mma16816(d[0][2*ntp],   a0, w[0], w[1]);
                    mma16816(d[0][2*ntp+1], a0, w[2], w[3]);
                    mma16816(d[1][2*ntp],   a1, w[0], w[1]);
                    mma16816(d[1][2*ntp+1], a1, w[2], w[3]);
                }
            }
            #pragma unroll
            for (int mt = 0; mt < 2; mt++) {
                int m0 = mt * 16 + (lane >> 2);
                #pragma unroll
                for (int nt = 0; nt < 4; nt++) {
                    int c = wid * 32 + nt * 8 + (lane & 3) * 2;
                    *(float2*)(sA1f + m0 * 132 + c)       = make_float2(d[mt][nt][0], d[mt][nt][1]);
                    *(float2*)(sA1f + (m0 + 8) * 132 + c) = make_float2(d[mt][nt][2], d[mt][nt][3]);
                }
            }
        } else {
            float d[2][6][4];
            #pragma unroll
            for (int mt = 0; mt < 2; mt++)
                #pragma unroll
                for (int nt = 0; nt < 6; nt++)
                    #pragma unroll
                    for (int z = 0; z < 4; z++) d[mt][nt][z] = 0.f;
            #pragma unroll
            for (int ks = 0; ks < 4; ks++) {
                uint32_t a0[4], a1[4];
                ldsm4(aB + ks * 32,        a0[0], a0[1], a0[2], a0[3]);
                ldsm4(aB + 2304 + ks * 32, a1[0], a1[1], a1[2], a1[3]);
                #pragma unroll
                for (int ntp = 0; ntp < 3; ntp++) {
                    uint32_t w[4];
                    ldsm4(wB + ntp * 2304 + ks * 32, w[0], w[1], w[2], w[3]);
                    mma16816(d[0][2*ntp],   a0, w[0], w[1]);
                    mma16816(d[0][2*ntp+1], a0, w[2], w[3]);
                    mma16816(d[1][2*ntp],   a1, w[0], w[1]);
                    mma16816(d[1][2*ntp+1], a1, w[2], w[3]);
                }
            }
            int mgrow = rowbase - 32;
            #pragma unroll
            for (int mt = 0; mt < 2; mt++) {
                int m0 = mgrow + mt * 16 + (lane >> 2);
                #pragma unroll
                for (int nt = 0; nt < 6; nt++) {
                    int c = colbase + nt * 8 + (lane & 3) * 2;
                    *(float2*)(sG2f + m0 * 196 + c)       = make_float2(d[mt][nt][0], d[mt][nt][1]);
                    *(float2*)(sG2f + (m0 + 8) * 196 + c) = make_float2(d[mt][nt][2], d[mt][nt][3]);
                }
            }
        }
        __syncthreads();

        // ---- o1: 32 rows x 384 cols (coalesced) ----
        #pragma unroll
        for (int i = 0; i < 24; i++) {
            int g = tid + i * 512;
            int row = g / 384, c = g - row * 384;
            int w = c / 3, kk = c - 3 * w;
            int nr = row0 + row;
            if (nr < n) {
                float val = sA1f[row * 132 + w] * sI2[row * 4 + 1 + kk]
                          + sG2f[(3 * row + kk) * 196 + w] * sI2[row * 4];
                out[(size_t)nr * OUT_STRIDE + 320 + c] = val;
            }
        }
        // ---- o2: 32 rows x 192 cols (coalesced) ----
        #pragma unroll
        for (int i = 0; i < 12; i++) {
            int g = tid + i * 512;
            int row = g / 192, c = g - row * 192;
            int w = c / 3, kk = c - 3 * w;
            int nr = row0 + row;
            if (nr < n) {
                int k1 = k1a[kk], k2 = k2a[kk];
                float val = sG2f[(3 * row + k1) * 196 + 128 + w] * sI2[row * 4 + 1 + k2]
                          - sG2f[(3 * row + k2) * 196 + 128 + w] * sI2[row * 4 + 1 + k1];
                out[(size_t)nr * OUT_STRIDE + 704 + c] = val;
            }
        }
        __syncthreads();
    }
}

extern "C" void kernel_launch(void* const* d_in, const int* in_sizes, int n_in,
                              void* d_out, int out_size)
{
    const float* in1   = (const float*)d_in[0];
    const float* in2   = (const float*)d_in[1];
    const float* Wa0   = (const float*)d_in[2];
    const float* Wb1o0 = (const float*)d_in[3];
    const float* Wa1   = (const float*)d_in[4];
    const float* Wb0   = (const float*)d_in[5];
    const float* Wo2   = (const float*)d_in[6];
    const float* bias  = (const float*)d_in[7];
    float* out = (float*)d_out;

    const int n = in_sizes[0] / 256;

    cudaFuncSetAttribute(k_o0,  cudaFuncAttributeMaxDynamicSharedMemorySize, A_SMEM);
    cudaFuncSetAttribute(k_o12, cudaFuncAttributeMaxDynamicSharedMemorySize, B_SMEM);

    int sms = 148;
    cudaDeviceGetAttribute(&sms, cudaDevAttrMultiProcessorCount, 0);

    const int chA = (n + A_RT - 1) / A_RT;
    const int chB = (n + B_RT - 1) / B_RT;
    const int gA = (2 * sms < chA) ? 2 * sms : chA;
    const int gB = (sms < chB) ? sms : chB;

    k_o12<<<gB, 512, B_SMEM>>>(in1, in2, Wa1, Wb0, Wo2, out, n, chB);
    k_o0 <<<gA, 256, A_SMEM>>>(in1, in2, Wa0, Wb1o0, bias, out, n, chA);
}

// round 10
// speedup vs baseline: 2.6416x; 1.7778x over previous
#include <cuda_runtime.h>
#include <cuda_fp16.h>
#include <cstdint>

#define PW0f 0.08838834764831845f
#define INV_SQRT3f 0.5773502691896258f
#define OUT_STRIDE 896

// ---------------- helpers ----------------
__device__ __forceinline__ uint32_t smem_u32(const void* p) {
    uint32_t a;
    asm("{ .reg .u64 t; cvta.to.shared.u64 t, %1; cvt.u32.u64 %0, t; }" : "=r"(a) : "l"(p));
    return a;
}
__device__ __forceinline__ void ldsm4(uint32_t addr, uint32_t& r0, uint32_t& r1,
                                      uint32_t& r2, uint32_t& r3) {
    asm volatile("ldmatrix.sync.aligned.m8n8.x4.shared.b16 {%0,%1,%2,%3}, [%4];"
                 : "=r"(r0), "=r"(r1), "=r"(r2), "=r"(r3) : "r"(addr));
}
__device__ __forceinline__ void mma16816(float* d, const uint32_t* a,
                                         uint32_t b0, uint32_t b1) {
    asm volatile("mma.sync.aligned.m16n8k16.row.col.f32.f16.f16.f32 "
                 "{%0,%1,%2,%3}, {%4,%5,%6,%7}, {%8,%9}, {%0,%1,%2,%3};"
                 : "+f"(d[0]), "+f"(d[1]), "+f"(d[2]), "+f"(d[3])
                 : "r"(a[0]), "r"(a[1]), "r"(a[2]), "r"(a[3]), "r"(b0), "r"(b1));
}
__device__ __forceinline__ unsigned short h16(float f) {
    return __half_as_ushort(__float2half(f));
}
__device__ __forceinline__ uint32_t pack2h(float f0, float f1) {
    return (uint32_t)h16(f0) | ((uint32_t)h16(f1) << 16);
}

// ===========================================================================
// Kernel A: o0 (cols 0..319).  Chunk 64 rows, 256 threads, 2 blocks/SM.
//   (unchanged from round 9 — 97 us)
// ===========================================================================
#define A_RT 64
#define AO_W    0
#define AO_A    87040
#define AO_BIAS 104448
#define A_SMEM  105728

__global__ __launch_bounds__(256, 2) void k_o0(
    const float* __restrict__ in1, const float* __restrict__ in2,
    const float* __restrict__ Wa0, const float* __restrict__ Wb1,
    const float* __restrict__ bias, float* __restrict__ out,
    int n, int nChunks)
{
    extern __shared__ char sm[];
    const uint32_t sb = smem_u32(sm);
    const int tid = threadIdx.x, lane = tid & 31, wid = tid >> 5;
    const int wm = wid & 1, wn = wid >> 1;

    for (int idx = tid; idx < 64 * 320; idx += 256) {
        int u = idx / 320, col = idx - u * 320;
        *(unsigned short*)(sm + AO_W + col * 272 + 2 * u)       = h16(PW0f * Wa0[idx]);
        *(unsigned short*)(sm + AO_W + col * 272 + 128 + 2 * u) = h16(PW0f * INV_SQRT3f * Wb1[idx]);
    }
    for (int i = tid; i < 320; i += 256) ((float*)(sm + AO_BIAS))[i] = bias[i];

    const int wlr = (lane & 7) + ((lane >> 4) & 1) * 8;
    const int wkh = (lane >> 3) & 1;
    const uint32_t aB = sb + AO_A + (uint32_t)(wm * 32 + (lane & 15)) * 272 + (lane >> 4) * 16;
    const uint32_t wB = sb + AO_W + (uint32_t)(wn * 80 + wlr) * 272 + wkh * 16;

    const int r = tid >> 2, p = tid & 3;

    __syncthreads();

    for (int chunk = blockIdx.x; chunk < nChunks; chunk += gridDim.x) {
        const int row0 = chunk * A_RT;

        {
            int nr = row0 + r;
            char* rowA = sm + AO_A + r * 272;
            if (nr < n) {
                const float* ip = in1 + (size_t)nr * 256;
                float4 iv = *(const float4*)(in2 + (size_t)nr * 4);
                if (p < 2) {
                    const float2* s = (const float2*)(ip + 32 * p);
                    #pragma unroll
                    for (int i = 0; i < 8; i++) {
                        float2 x0 = s[2*i], x1 = s[2*i+1];
                        uint2 v = { pack2h(x0.x * iv.x, x0.y * iv.x),
                                    pack2h(x1.x * iv.x, x1.y * iv.x) };
                        *(uint2*)(rowA + 64 * p + 8 * i) = v;
                    }
                } else {
                    int j0 = 32 * (p - 2);
                    #pragma unroll
                    for (int b = 0; b < 4; b++) {
                        const float* vp = ip + 64 + 3 * j0 + 24 * b;
                        float4 f0 = *(const float4*)(vp);
                        float4 f1 = *(const float4*)(vp + 4);
                        float4 f2 = *(const float4*)(vp + 8);
                        float4 f3 = *(const float4*)(vp + 12);
                        float4 f4 = *(const float4*)(vp + 16);
                        float4 f5 = *(const float4*)(vp + 20);
                        float d0 = f0.x*iv.y + f0.y*iv.z + f0.z*iv.w;
                        float d1 = f0.w*iv.y + f1.x*iv.z + f1.y*iv.w;
                        float d2 = f1.z*iv.y + f1.w*iv.z + f2.x*iv.w;
                        float d3 = f2.y*iv.y + f2.z*iv.z + f2.w*iv.w;
                        float d4 = f3.x*iv.y + f3.y*iv.z + f3.z*iv.w;
                        float d5 = f3.w*iv.y + f4.x*iv.z + f4.y*iv.w;
                        float d6 = f4.z*iv.y + f4.w*iv.z + f5.x*iv.w;
                        float d7 = f5.y*iv.y + f5.z*iv.z + f5.w*iv.w;
                        uint4 v = { pack2h(d0, d1), pack2h(d2, d3),
                                    pack2h(d4, d5), pack2h(d6, d7) };
                        *(uint4*)(rowA + 128 + 2 * j0 + 16 * b) = v;
                    }
                }
            } else {
                if (p < 2) {
                    #pragma unroll
                    for (int i = 0; i < 8; i++) *(uint2*)(rowA + 64 * p + 8 * i) = make_uint2(0, 0);
                } else {
                    int j0 = 32 * (p - 2);
                    #pragma unroll
                    for (int b = 0; b < 4; b++)
                        *(uint4*)(rowA + 128 + 2 * j0 + 16 * b) = make_uint4(0, 0, 0, 0);
                }
            }
        }
        __syncthreads();

        float d[2][10][4];
        #pragma unroll
        for (int mt = 0; mt < 2; mt++)
            #pragma unroll
            for (int nt = 0; nt < 10; nt++)
                #pragma unroll
                for (int z = 0; z < 4; z++) d[mt][nt][z] = 0.f;

        #pragma unroll
        for (int ks = 0; ks < 8; ks++) {
            uint32_t a0[4], a1[4];
            ldsm4(aB + ks * 32,        a0[0], a0[1], a0[2], a0[3]);
            ldsm4(aB + 4352 + ks * 32, a1[0], a1[1], a1[2], a1[3]);
            #pragma unroll
            for (int nt2 = 0; nt2 < 5; nt2++) {
                uint32_t w[4];
                ldsm4(wB + nt2 * 4352 + ks * 32, w[0], w[1], w[2], w[3]);
                mma16816(d[0][2*nt2],   a0, w[0], w[1]);
                mma16816(d[0][2*nt2+1], a0, w[2], w[3]);
                mma16816(d[1][2*nt2],   a1, w[0], w[1]);
                mma16816(d[1][2*nt2+1], a1, w[2], w[3]);
            }
        }

        {
            const float* sBias = (const float*)(sm + AO_BIAS);
            #pragma unroll
            for (int mt = 0; mt < 2; mt++) {
                int rr0 = row0 + wm * 32 + mt * 16 + (lane >> 2);
                int rr1 = rr0 + 8;
                #pragma unroll
                for (int nt = 0; nt < 10; nt++) {
                    int col = wn * 80 + nt * 8 + (lane & 3) * 2;
                    float b0 = sBias[col], b1 = sBias[col + 1];
                    if (rr0 < n) {
                        float2 v = { d[mt][nt][0] + b0, d[mt][nt][1] + b1 };
                        *(float2*)(out + (size_t)rr0 * OUT_STRIDE + col) = v;
                    }
                    if (rr1 < n) {
                        float2 v = { d[mt][nt][2] + b0, d[mt][nt][3] + b1 };
                        *(float2*)(out + (size_t)rr1 * OUT_STRIDE + col) = v;
                    }
                }
            }
        }
        __syncthreads();
    }
}

// ===========================================================================
// Kernel B (restructured): o1 + o2 as DIRECT GEMM outputs.  Chunk 32 rows,
// 256 threads, 2 blocks/SM.
//   A1[m=3r+k][K=128] = [ sa[r,u]*v1[r,k] | vb[r,u,k]*s0[r] ]
//   W1[w][K=128]      = PW0*[ Wa1[u][w] | Wb0[u][w] ]
//     -> o1[r, 320+3w+k] = (A1 @ W1')[m][w]
//   A2[m=3r+k][K=64]  = cross(vb,v1)[r,u,k]
//   W2[w][K=64]       = PW0*Wo2[u][w]
//     -> o2[r, 704+3w+k] = (A2 @ W2')[m][w]
//   8 warps: o1 = 2 m-groups(48) x 4 n-groups(32); o2 = 2 x 4 n-groups(16).
// ===========================================================================
#define B_RT 32
#define BO_W1 0          /* 128 x 272 = 34816 */
#define BO_W2 34816      /* 64 x 144  =  9216 */
#define BO_A1 44032      /* 96 x 272  = 26112 */
#define BO_A2 70144      /* 96 x 144  = 13824 */
#define B_SMEM 83968

__global__ __launch_bounds__(256, 2) void k_o12(
    const float* __restrict__ in1, const float* __restrict__ in2,
    const float* __restrict__ Wa1, const float* __restrict__ Wb0,
    const float* __restrict__ Wo2, float* __restrict__ out,
    int n, int nChunks)
{
    extern __shared__ char sm[];
    const uint32_t sb = smem_u32(sm);
    const int tid = threadIdx.x, lane = tid & 31, wid = tid >> 5;

    // stage weights, PW0 folded
    for (int idx = tid; idx < 64 * 128; idx += 256) {
        int u = idx >> 7, w = idx & 127;
        *(unsigned short*)(sm + BO_W1 + w * 272 + 2 * u)       = h16(PW0f * Wa1[idx]);
        *(unsigned short*)(sm + BO_W1 + w * 272 + 128 + 2 * u) = h16(PW0f * Wb0[idx]);
    }
    for (int idx = tid; idx < 64 * 64; idx += 256) {
        int u = idx >> 6, w = idx & 63;
        *(unsigned short*)(sm + BO_W2 + w * 144 + 2 * u) = h16(PW0f * Wo2[idx]);
    }

    const int mgrp = wid & 1;          // 0,1 -> m rows mgrp*48
    const int ngrp = wid >> 1;         // 0..3
    const int wlr = (lane & 7) + ((lane >> 4) & 1) * 8;
    const int wkh = (lane >> 3) & 1;

    const uint32_t a1B = sb + BO_A1 + (uint32_t)(mgrp * 48 + (lane & 15)) * 272 + (lane >> 4) * 16;
    const uint32_t w1B = sb + BO_W1 + (uint32_t)(ngrp * 32 + wlr) * 272 + wkh * 16;
    const uint32_t a2B = sb + BO_A2 + (uint32_t)(mgrp * 48 + (lane & 15)) * 144 + (lane >> 4) * 16;
    const uint32_t w2B = sb + BO_W2 + (uint32_t)(ngrp * 16 + wlr) * 144 + wkh * 16;

    const int r = tid >> 3, t = tid & 7;   // 8 threads per row, u0 = 8t

    __syncthreads();

    for (int chunk = blockIdx.x; chunk < nChunks; chunk += gridDim.x) {
        const int row0 = chunk * B_RT;

        // ---- convert + STS: build A1 (sa*v1 | vb*s0) and A2 (cross) ----
        {
            int nr = row0 + r;
            int u0 = 8 * t;
            if (nr < n) {
                const float* ip = in1 + (size_t)nr * 256;
                float4 iv = *(const float4*)(in2 + (size_t)nr * 4);
                float sa[8], vb[3][8];
                {
                    float4 s0v = *(const float4*)(ip + u0);
                    float4 s1v = *(const float4*)(ip + u0 + 4);
                    sa[0]=s0v.x; sa[1]=s0v.y; sa[2]=s0v.z; sa[3]=s0v.w;
                    sa[4]=s1v.x; sa[5]=s1v.y; sa[6]=s1v.z; sa[7]=s1v.w;
                    const float* vp = ip + 64 + 3 * u0;
                    float4 f0 = *(const float4*)(vp);
                    float4 f1 = *(const float4*)(vp + 4);
                    float4 f2 = *(const float4*)(vp + 8);
                    float4 f3 = *(const float4*)(vp + 12);
                    float4 f4 = *(const float4*)(vp + 16);
                    float4 f5 = *(const float4*)(vp + 20);
                    vb[0][0]=f0.x; vb[1][0]=f0.y; vb[2][0]=f0.z;
                    vb[0][1]=f0.w; vb[1][1]=f1.x; vb[2][1]=f1.y;
                    vb[0][2]=f1.z; vb[1][2]=f1.w; vb[2][2]=f2.x;
                    vb[0][3]=f2.y; vb[1][3]=f2.z; vb[2][3]=f2.w;
                    vb[0][4]=f3.x; vb[1][4]=f3.y; vb[2][4]=f3.z;
                    vb[0][5]=f3.w; vb[1][5]=f4.x; vb[2][5]=f4.y;
                    vb[0][6]=f4.z; vb[1][6]=f4.w; vb[2][6]=f5.x;
                    vb[0][7]=f5.y; vb[1][7]=f5.z; vb[2][7]=f5.w;
                }
                float v1c[3] = { iv.y, iv.z, iv.w };
                float s0 = iv.x;
                #pragma unroll
                for (int k = 0; k < 3; k++) {
                    int m = 3 * r + k;
                    char* row1 = sm + BO_A1 + m * 272;
                    char* row2 = sm + BO_A2 + m * 144;
                    // sa * v1[k]
                    uint4 va = { pack2h(sa[0]*v1c[k], sa[1]*v1c[k]),
                                 pack2h(sa[2]*v1c[k], sa[3]*v1c[k]),
                                 pack2h(sa[4]*v1c[k], sa[5]*v1c[k]),
                                 pack2h(sa[6]*v1c[k], sa[7]*v1c[k]) };
                    *(uint4*)(row1 + 2 * u0) = va;
                    // vb[k] * s0
                    uint4 vbv = { pack2h(vb[k][0]*s0, vb[k][1]*s0),
                                  pack2h(vb[k][2]*s0, vb[k][3]*s0),
                                  pack2h(vb[k][4]*s0, vb[k][5]*s0),
                                  pack2h(vb[k][6]*s0, vb[k][7]*s0) };
                    *(uint4*)(row1 + 128 + 2 * u0) = vbv;
                    // cross component k: cr_k = vb[k1]*v1[k2] - vb[k2]*v1[k1]
                    int k1 = (k == 0) ? 1 : (k == 1) ? 2 : 0;
                    int k2 = (k == 0) ? 2 : (k == 1) ? 0 : 1;
                    float cr[8];
                    #pragma unroll
                    for (int i = 0; i < 8; i++)
                        cr[i] = vb[k1][i] * v1c[k2] - vb[k2][i] * v1c[k1];
                    uint4 vc = { pack2h(cr[0], cr[1]), pack2h(cr[2], cr[3]),
                                 pack2h(cr[4], cr[5]), pack2h(cr[6], cr[7]) };
                    *(uint4*)(row2 + 2 * u0) = vc;
                }
            } else {
                uint4 z = make_uint4(0, 0, 0, 0);
                #pragma unroll
                for (int k = 0; k < 3; k++) {
                    int m = 3 * r + k;
                    *(uint4*)(sm + BO_A1 + m * 272 + 2 * u0) = z;
                    *(uint4*)(sm + BO_A1 + m * 272 + 128 + 2 * u0) = z;
                    *(uint4*)(sm + BO_A2 + m * 144 + 2 * u0) = z;
                }
            }
        }
        __syncthreads();

        // ---- GEMM 1: o1 (M=96 per m-group 48, N=32/warp, K=128) ----
        float d1[3][4][4];
        #pragma unroll
        for (int mt = 0; mt < 3; mt++)
            #pragma unroll
            for (int nt = 0; nt < 4; nt++)
                #pragma unroll
                for (int z = 0; z < 4; z++) d1[mt][nt][z] = 0.f;

        #pragma unroll
        for (int ks = 0; ks < 8; ks++) {
            uint32_t a0[4], a1[4], a2[4];
            ldsm4(a1B + ks * 32,            a0[0], a0[1], a0[2], a0[3]);
            ldsm4(a1B + 4352 + ks * 32,     a1[0], a1[1], a1[2], a1[3]);
            ldsm4(a1B + 2 * 4352 + ks * 32, a2[0], a2[1], a2[2], a2[3]);
            #pragma unroll
            for (int np = 0; np < 2; np++) {
                uint32_t w[4];
                ldsm4(w1B + np * 4352 + ks * 32, w[0], w[1], w[2], w[3]);
                mma16816(d1[0][2*np],   a0, w[0], w[1]);
                mma16816(d1[0][2*np+1], a0, w[2], w[3]);
                mma16816(d1[1][2*np],   a1, w[0], w[1]);
                mma16816(d1[1][2*np+1], a1, w[2], w[3]);
                mma16816(d1[2][2*np],   a2, w[0], w[1]);
                mma16816(d1[2][2*np+1], a2, w[2], w[3]);
            }
        }

        // ---- GEMM 2: o2 (N=16/warp, K=64) ----
        float d2[3][2][4];
        #pragma unroll
        for (int mt = 0; mt < 3; mt++)
            #pragma unroll
            for (int nt = 0; nt < 2; nt++)
                #pragma unroll
                for (int z = 0; z < 4; z++) d2[mt][nt][z] = 0.f;

        #pragma unroll
        for (int ks = 0; ks < 4; ks++) {
            uint32_t a0[4], a1[4], a2[4], w[4];
            ldsm4(a2B + ks * 32,            a0[0], a0[1], a0[2], a0[3]);
            ldsm4(a2B + 2304 + ks * 32,     a1[0], a1[1], a1[2], a1[3]);
            ldsm4(a2B + 2 * 2304 + ks * 32, a2[0], a2[1], a2[2], a2[3]);
            ldsm4(w2B + ks * 32, w[0], w[1], w[2], w[3]);
            mma16816(d2[0][0], a0, w[0], w[1]);
            mma16816(d2[0][1], a0, w[2], w[3]);
            mma16816(d2[1][0], a1, w[0], w[1]);
            mma16816(d2[1][1], a1, w[2], w[3]);
            mma16816(d2[2][0], a2, w[0], w[1]);
            mma16816(d2[2][1], a2, w[2], w[3]);
        }

        // ---- direct epilogue ----
        #pragma unroll
        for (int mt = 0; mt < 3; mt++) {
            #pragma unroll
            for (int half = 0; half < 2; half++) {
                int m = mgrp * 48 + mt * 16 + half * 8 + (lane >> 2);
                int rr = m / 3, kk = m - 3 * rr;
                int nr = row0 + rr;
                if (nr < n) {
                    float* op1 = out + (size_t)nr * OUT_STRIDE + 320 + kk;
                    #pragma unroll
                    for (int nt = 0; nt < 4; nt++) {
                        int w = ngrp * 32 + nt * 8 + (lane & 3) * 2;
                        op1[3 * w]     = d1[mt][nt][2 * half];
                        op1[3 * w + 3] = d1[mt][nt][2 * half + 1];
                    }
                    float* op2 = out + (size_t)nr * OUT_STRIDE + 704 + kk;
                    #pragma unroll
                    for (int nt = 0; nt < 2; nt++) {
                        int w = ngrp * 16 + nt * 8 + (lane & 3) * 2;
                        op2[3 * w]     = d2[mt][nt][2 * half];
                        op2[3 * w + 3] = d2[mt][nt][2 * half + 1];
                    }
                }
            }
        }
        __syncthreads();
    }
}

extern "C" void kernel_launch(void* const* d_in, const int* in_sizes, int n_in,
                              void* d_out, int out_size)
{
    const float* in1   = (const float*)d_in[0];
    const float* in2   = (const float*)d_in[1];
    const float* Wa0   = (const float*)d_in[2];
    const float* Wb1o0 = (const float*)d_in[3];
    const float* Wa1   = (const float*)d_in[4];
    const float* Wb0   = (const float*)d_in[5];
    const float* Wo2   = (const float*)d_in[6];
    const float* bias  = (const float*)d_in[7];
    float* out = (float*)d_out;

    const int n = in_sizes[0] / 256;

    cudaFuncSetAttribute(k_o0,  cudaFuncAttributeMaxDynamicSharedMemorySize, A_SMEM);
    cudaFuncSetAttribute(k_o12, cudaFuncAttributeMaxDynamicSharedMemorySize, B_SMEM);

    int sms = 148;
    cudaDeviceGetAttribute(&sms, cudaDevAttrMultiProcessorCount, 0);

    const int chA = (n + A_RT - 1) / A_RT;
    const int chB = (n + B_RT - 1) / B_RT;
    const int gA = (2 * sms < chA) ? 2 * sms : chA;
    const int gB = (2 * sms < chB) ? 2 * sms : chB;

    k_o12<<<gB, 256, B_SMEM>>>(in1, in2, Wa1, Wb0, Wo2, out, n, chB);
    k_o0 <<<gA, 256, A_SMEM>>>(in1, in2, Wa0, Wb1o0, bias, out, n, chA);
}